// round 11
// baseline (speedup 1.0000x reference)
#include <cuda_runtime.h>
#include <cuda_fp16.h>
#include <math.h>

#define DHH 128
#define NMAX 50000
#define EMAX 800000
#define MT 64            // nodes per C tile
#define NTILES 16        // 16 n-tiles of 8 = 128 output feats
#define KST 16           // K-steps of 16 over fused K=256
#define THREADS 512
#define SCAN_B 256
#define A_STRIDE 132                               // 128 k-pairs + 4 pad
#define SMEM_W_BYTES (KST * NTILES * 32 * 16)      // 8192 uint4 = 131072
#define SMEM_A_UINTS (MT * A_STRIDE)               // 8448
#define SMEM_TOTAL_BYTES (SMEM_W_BYTES + 2 * SMEM_A_UINTS * 4)

// Scratch (allocation-free: static device globals)
__device__ __align__(16) float4 g_s [NMAX * DHH / 4];
__device__ __align__(16) float4 g_h1[NMAX * DHH / 4];
__device__ __align__(16) float4 g_h2[NMAX * DHH / 4];
// fp16 read-mirrors for the gather pass (64 fp16x2 words per node)
__device__ __align__(16) unsigned g_xh [NMAX * 64];
__device__ __align__(16) unsigned g_h1h[NMAX * 64];
__device__ __align__(16) unsigned g_h2h[NMAX * 64];
__device__ __align__(16) uint4 g_wfrag[2 * 8192];  // pre-split W fragments
__device__ int g_deg[NMAX];
__device__ int g_tmp[NMAX];
__device__ int g_rowptr[NMAX + 1];
__device__ int g_cursor[NMAX];
__device__ int g_esrc[EMAX];
__device__ int g_psum[256];

// ---------------------------------------------------------------------------
// fp16 / bf16 helpers
// ---------------------------------------------------------------------------
__device__ __forceinline__ unsigned packh2(float a, float b) {
    __half2 h = __floats2half2_rn(a, b);
    return *reinterpret_cast<unsigned*>(&h);
}
__device__ __forceinline__ float2 unpackh2(unsigned u) {
    __half2 h = *reinterpret_cast<__half2*>(&u);
    return __half22float2(h);
}

__device__ __forceinline__ unsigned pack_bf16x2(float lo, float hi) {
    unsigned u;
    asm("cvt.rn.bf16x2.f32 %0, %1, %2;" : "=r"(u) : "f"(hi), "f"(lo));
    return u;
}

__device__ __forceinline__ void split2(float x, float y, unsigned& hi, unsigned& lo) {
    hi = pack_bf16x2(x, y);
    float xh = __uint_as_float(hi << 16);
    float yh = __uint_as_float(hi & 0xffff0000u);
    lo = pack_bf16x2(x - xh, y - yh);
}

__device__ __forceinline__ void mma16(float* c, const unsigned* a, unsigned b0, unsigned b1) {
    asm volatile("mma.sync.aligned.m16n8k16.row.col.f32.bf16.bf16.f32 "
        "{%0,%1,%2,%3}, {%4,%5,%6,%7}, {%8,%9}, {%0,%1,%2,%3};"
        : "+f"(c[0]), "+f"(c[1]), "+f"(c[2]), "+f"(c[3])
        : "r"(a[0]), "r"(a[1]), "r"(a[2]), "r"(a[3]), "r"(b0), "r"(b1));
}

// ---------------------------------------------------------------------------
// Convert x (f32) -> fp16 mirror
// ---------------------------------------------------------------------------
__global__ void convert_x(const float2* __restrict__ x, unsigned* __restrict__ xh, int n) {
    int i = blockIdx.x * blockDim.x + threadIdx.x;
    if (i < n) {
        float2 v = __ldg(&x[i]);
        xh[i] = packh2(v.x, v.y);
    }
}

// ---------------------------------------------------------------------------
// Prep: split W into bf16 hi/lo fragment order (see layout comment R4).
// ---------------------------------------------------------------------------
__global__ void prep_w(const float* __restrict__ W1l, const float* __restrict__ W1r,
                       const float* __restrict__ Whl, const float* __restrict__ Whr) {
    int idx = blockIdx.x * blockDim.x + threadIdx.x;
    if (idx >= 16384) return;
    int layer = idx >> 13;
    int rem = idx & 8191;
    int S = rem >> 9;
    int T = (rem >> 5) & 15;
    int lane = rem & 31;
    const float* W = (S < 8) ? (layer ? Whl : W1l) : (layer ? Whr : W1r);
    int k0 = (S & 7) * 16;
    int row = T * 8 + (lane >> 2);
    int cc = lane & 3;
    const float* p = W + row * DHH + k0 + 2 * cc;
    unsigned h0, l0, h1, l1;
    split2(__ldg(&p[0]), __ldg(&p[1]), h0, l0);
    split2(__ldg(&p[8]), __ldg(&p[9]), h1, l1);
    g_wfrag[idx] = make_uint4(h0, h1, l0, l1);
}

// ---------------------------------------------------------------------------
// CSR build: histogram -> block scan -> offsets -> fill
// ---------------------------------------------------------------------------
__global__ void hist_k(const int* __restrict__ ei, int E, int* __restrict__ deg) {
    int e = blockIdx.x * blockDim.x + threadIdx.x;
    if (e < E) atomicAdd(&deg[ei[E + e]], 1);
}

__global__ void scan1_k(const int* __restrict__ deg, int N,
                        int* __restrict__ tmp, int* __restrict__ psum) {
    __shared__ int sh[SCAN_B];
    int i = blockIdx.x * SCAN_B + threadIdx.x;
    int v = (i < N) ? deg[i] : 0;
    sh[threadIdx.x] = v;
    __syncthreads();
    for (int off = 1; off < SCAN_B; off <<= 1) {
        int add = (threadIdx.x >= off) ? sh[threadIdx.x - off] : 0;
        __syncthreads();
        sh[threadIdx.x] += add;
        __syncthreads();
    }
    if (i < N) tmp[i] = sh[threadIdx.x] - v;            // exclusive within block
    if (threadIdx.x == SCAN_B - 1) psum[blockIdx.x] = sh[threadIdx.x];
}

__global__ void scan2_k(int* __restrict__ psum, int nb) {
    __shared__ int sh[SCAN_B];
    int t = threadIdx.x;
    int v = (t < nb) ? psum[t] : 0;
    sh[t] = v;
    __syncthreads();
    for (int off = 1; off < SCAN_B; off <<= 1) {
        int add = (t >= off) ? sh[t - off] : 0;
        __syncthreads();
        sh[t] += add;
        __syncthreads();
    }
    if (t < nb) psum[t] = sh[t] - v;                    // exclusive
}

__global__ void scan3_k(const int* __restrict__ tmp, const int* __restrict__ psum,
                        int N, int E, int* __restrict__ rowptr, int* __restrict__ cursor) {
    int i = blockIdx.x * SCAN_B + threadIdx.x;
    if (i < N) {
        int v = tmp[i] + psum[blockIdx.x];
        rowptr[i] = v;
        cursor[i] = v;
    }
    if (i == 0) rowptr[N] = E;
}

__global__ void fill_k(const int* __restrict__ ei, int E,
                       int* __restrict__ cursor, int* __restrict__ esrc) {
    int e = blockIdx.x * blockDim.x + threadIdx.x;
    if (e < E) {
        int dst = ei[E + e];
        int p = atomicAdd(&cursor[dst], 1);
        esrc[p] = ei[e];
    }
}

// ---------------------------------------------------------------------------
// Gather: one warp per dst node. Reads the fp16 MIRROR (half the bytes of
// f32), accumulates f32, writes mean in f32 for the GEMM.
// ---------------------------------------------------------------------------
__global__ void gather_k(const uint2* __restrict__ feath, const int* __restrict__ rowptr,
                         const int* __restrict__ esrc, float4* __restrict__ s, int N) {
    int n = blockIdx.x * 8 + (threadIdx.x >> 5);
    if (n >= N) return;
    int lane = threadIdx.x & 31;
    int beg = __ldg(&rowptr[n]);
    int end = __ldg(&rowptr[n + 1]);

    float4 a0 = make_float4(0.f, 0.f, 0.f, 0.f);
    float4 a1 = make_float4(0.f, 0.f, 0.f, 0.f);
    float4 a2 = make_float4(0.f, 0.f, 0.f, 0.f);
    float4 a3 = make_float4(0.f, 0.f, 0.f, 0.f);

    int e = beg;
    for (; e + 4 <= end; e += 4) {
        int s0 = __ldg(&esrc[e]), s1 = __ldg(&esrc[e + 1]);
        int s2 = __ldg(&esrc[e + 2]), s3 = __ldg(&esrc[e + 3]);
        uint2 u0 = __ldg(&feath[s0 * 32 + lane]);
        uint2 u1 = __ldg(&feath[s1 * 32 + lane]);
        uint2 u2 = __ldg(&feath[s2 * 32 + lane]);
        uint2 u3 = __ldg(&feath[s3 * 32 + lane]);
        float2 p, q;
        p = unpackh2(u0.x); q = unpackh2(u0.y);
        a0.x += p.x; a0.y += p.y; a0.z += q.x; a0.w += q.y;
        p = unpackh2(u1.x); q = unpackh2(u1.y);
        a1.x += p.x; a1.y += p.y; a1.z += q.x; a1.w += q.y;
        p = unpackh2(u2.x); q = unpackh2(u2.y);
        a2.x += p.x; a2.y += p.y; a2.z += q.x; a2.w += q.y;
        p = unpackh2(u3.x); q = unpackh2(u3.y);
        a3.x += p.x; a3.y += p.y; a3.z += q.x; a3.w += q.y;
    }
    for (; e < end; e++) {
        int s0 = __ldg(&esrc[e]);
        uint2 u0 = __ldg(&feath[s0 * 32 + lane]);
        float2 p = unpackh2(u0.x), q = unpackh2(u0.y);
        a0.x += p.x; a0.y += p.y; a0.z += q.x; a0.w += q.y;
    }

    float inv = 1.0f / fmaxf((float)(end - beg), 1.0f);
    float4 r;
    r.x = (a0.x + a1.x + a2.x + a3.x) * inv;
    r.y = (a0.y + a1.y + a2.y + a3.y) * inv;
    r.z = (a0.z + a1.z + a2.z + a3.z) * inv;
    r.w = (a0.w + a1.w + a2.w + a3.w) * inv;
    s[n * 32 + lane] = r;
}

// ---------------------------------------------------------------------------
// Fused SAGE layer: C = act([agg | x] . [Wl|Wr]^T + bl), split-bf16 mma.
// f32 in / f32 out, PLUS an fp16 mirror write of the output for the next
// gather pass.
// ---------------------------------------------------------------------------
template <int ACT>
__global__ __launch_bounds__(THREADS, 1)
void sage_bf16(const float* __restrict__ x, const float* __restrict__ s,
               const uint4* __restrict__ wfrag, const float* __restrict__ bl,
               float* __restrict__ out, unsigned* __restrict__ outh, int N) {
    extern __shared__ char smemraw[];
    uint4*    shW  = (uint4*)smemraw;                       // [KST*NTILES*32]
    unsigned* shAh = (unsigned*)(smemraw + SMEM_W_BYTES);   // [MT][A_STRIDE]
    unsigned* shAl = shAh + SMEM_A_UINTS;

    int t = threadIdx.x;
    int w = t >> 5, lane = t & 31;
    int r = lane >> 2, c = lane & 3;
    int g = w >> 2;        // row-group 0..3
    int q = w & 3;         // tile quarter 0..3
    int mbase = g * 16;

    #pragma unroll
    for (int i = 0; i < 16; i++)
        shW[t + i * THREADS] = __ldg(&wfrag[t + i * THREADS]);

    float bias0[4], bias1[4];
    #pragma unroll
    for (int i = 0; i < 4; i++) {
        int colg = (q * 4 + i) * 8 + 2 * c;
        bias0[i] = __ldg(&bl[colg]);
        bias1[i] = __ldg(&bl[colg + 1]);
    }

    int mtiles = (N + MT - 1) / MT;
    for (int tile = blockIdx.x; tile < mtiles; tile += gridDim.x) {
        __syncthreads();
        int n0 = tile * MT;

        #pragma unroll
        for (int i = 0; i < 8; i++) {
            int flat = t + i * THREADS;
            int row = flat >> 6;
            int c4 = flat & 63;
            int node = n0 + row;
            float4 v = make_float4(0.f, 0.f, 0.f, 0.f);
            if (node < N) {
                if (c4 < 32)
                    v = __ldg((const float4*)s + (long long)node * 32 + c4);
                else
                    v = __ldg((const float4*)x + (long long)node * 32 + (c4 - 32));
            }
            unsigned h01, l01, h23, l23;
            split2(v.x, v.y, h01, l01);
            split2(v.z, v.w, h23, l23);
            int base = row * A_STRIDE + c4 * 2;
            *(uint2*)&shAh[base] = make_uint2(h01, h23);
            *(uint2*)&shAl[base] = make_uint2(l01, l23);
        }
        __syncthreads();

        float acc[4][4];
        #pragma unroll
        for (int T = 0; T < 4; T++)
            acc[T][0] = acc[T][1] = acc[T][2] = acc[T][3] = 0.f;

        #pragma unroll 4
        for (int S = 0; S < KST; S++) {
            int ra = (mbase + r) * A_STRIDE + S * 8 + c;
            int rb = (mbase + r + 8) * A_STRIDE + S * 8 + c;
            unsigned ah[4], al[4];
            ah[0] = shAh[ra]; ah[1] = shAh[rb]; ah[2] = shAh[ra + 4]; ah[3] = shAh[rb + 4];
            al[0] = shAl[ra]; al[1] = shAl[rb]; al[2] = shAl[ra + 4]; al[3] = shAl[rb + 4];
            #pragma unroll
            for (int T = 0; T < 4; T++) {
                uint4 b = shW[(S * NTILES + q * 4 + T) * 32 + lane];
                mma16(acc[T], al, b.x, b.y);   // al*bh
                mma16(acc[T], ah, b.z, b.w);   // ah*bl
                mma16(acc[T], ah, b.x, b.y);   // ah*bh
            }
        }

        #pragma unroll
        for (int T = 0; T < 4; T++) {
            int colg = (q * 4 + T) * 8 + 2 * c;
            float v0 = acc[T][0] + bias0[T], v1 = acc[T][1] + bias1[T];
            float v2 = acc[T][2] + bias0[T], v3 = acc[T][3] + bias1[T];
            if (ACT == 0) {
                v0 = fmaxf(v0, 0.f); v1 = fmaxf(v1, 0.f);
                v2 = fmaxf(v2, 0.f); v3 = fmaxf(v3, 0.f);
            } else {
                v0 = (v0 > 0.f) ? v0 : expm1f(v0);
                v1 = (v1 > 0.f) ? v1 : expm1f(v1);
                v2 = (v2 > 0.f) ? v2 : expm1f(v2);
                v3 = (v3 > 0.f) ? v3 : expm1f(v3);
            }
            int node0 = n0 + mbase + r;
            if (node0 < N) {
                *(float2*)&out[(long long)node0 * DHH + colg] = make_float2(v0, v1);
                outh[node0 * 64 + (colg >> 1)] = packh2(v0, v1);
            }
            if (node0 + 8 < N) {
                *(float2*)&out[(long long)(node0 + 8) * DHH + colg] = make_float2(v2, v3);
                outh[(node0 + 8) * 64 + (colg >> 1)] = packh2(v2, v3);
            }
        }
    }
}

// ---------------------------------------------------------------------------
// Output layer (DOUT=8) + log_softmax. One warp per node. f32 inputs (R9).
// ---------------------------------------------------------------------------
__global__ void sage_out_k(const float* __restrict__ x, const float* __restrict__ s,
                           const float* __restrict__ Wl, const float* __restrict__ bl,
                           const float* __restrict__ Wr,
                           float* __restrict__ out, int N) {
    long long tid = (long long)blockIdx.x * blockDim.x + threadIdx.x;
    int n = (int)(tid >> 5);
    if (n >= N) return;
    int lane = (int)(tid & 31);

    float acc[8];
    #pragma unroll
    for (int j = 0; j < 8; j++) acc[j] = 0.0f;

    #pragma unroll
    for (int ch = 0; ch < 4; ch++) {
        int k = lane + ch * 32;
        float sv = s[(long long)n * DHH + k];
        float xv = x[(long long)n * DHH + k];
        #pragma unroll
        for (int j = 0; j < 8; j++) {
            acc[j] = fmaf(sv, __ldg(&Wl[j * DHH + k]), acc[j]);
            acc[j] = fmaf(xv, __ldg(&Wr[j * DHH + k]), acc[j]);
        }
    }

    #pragma unroll
    for (int j = 0; j < 8; j++) {
        #pragma unroll
        for (int off = 16; off > 0; off >>= 1)
            acc[j] += __shfl_xor_sync(0xffffffff, acc[j], off);
    }

    if (lane == 0) {
        float h[8];
        float m = -1e30f;
        #pragma unroll
        for (int j = 0; j < 8; j++) {
            h[j] = acc[j] + bl[j];
            m = fmaxf(m, h[j]);
        }
        float sum = 0.0f;
        #pragma unroll
        for (int j = 0; j < 8; j++) sum += expf(h[j] - m);
        float lse = logf(sum) + m;
        #pragma unroll
        for (int j = 0; j < 8; j++) out[(long long)n * 8 + j] = h[j] - lse;
    }
}

// ---------------------------------------------------------------------------
extern "C" void kernel_launch(void* const* d_in, const int* in_sizes, int n_in,
                              void* d_out, int out_size) {
    const float* x   = (const float*)d_in[0];
    const int*   ei  = (const int*)d_in[1];
    // d_in[2] = edge_attr, unused
    const float* W1l = (const float*)d_in[3];
    const float* b1l = (const float*)d_in[4];
    const float* W1r = (const float*)d_in[5];
    const float* Whl = (const float*)d_in[6];
    const float* bhl = (const float*)d_in[7];
    const float* Whr = (const float*)d_in[8];
    const float* W2l = (const float*)d_in[9];
    const float* b2l = (const float*)d_in[10];
    const float* W2r = (const float*)d_in[11];
    float* out = (float*)d_out;

    int N = in_sizes[0] / DHH;
    int E = in_sizes[1] / 2;

    float4 *s, *h1, *h2;
    unsigned *xh, *h1h, *h2h;
    uint4* wfrag;
    int *deg, *tmp, *rowptr, *cursor, *esrc, *psum;
    cudaGetSymbolAddress((void**)&s, g_s);
    cudaGetSymbolAddress((void**)&h1, g_h1);
    cudaGetSymbolAddress((void**)&h2, g_h2);
    cudaGetSymbolAddress((void**)&xh, g_xh);
    cudaGetSymbolAddress((void**)&h1h, g_h1h);
    cudaGetSymbolAddress((void**)&h2h, g_h2h);
    cudaGetSymbolAddress((void**)&wfrag, g_wfrag);
    cudaGetSymbolAddress((void**)&deg, g_deg);
    cudaGetSymbolAddress((void**)&tmp, g_tmp);
    cudaGetSymbolAddress((void**)&rowptr, g_rowptr);
    cudaGetSymbolAddress((void**)&cursor, g_cursor);
    cudaGetSymbolAddress((void**)&esrc, g_esrc);
    cudaGetSymbolAddress((void**)&psum, g_psum);

    cudaFuncSetAttribute(sage_bf16<0>, cudaFuncAttributeMaxDynamicSharedMemorySize,
                         SMEM_TOTAL_BYTES);
    cudaFuncSetAttribute(sage_bf16<1>, cudaFuncAttributeMaxDynamicSharedMemorySize,
                         SMEM_TOTAL_BYTES);

    int egrid = (E + 255) / 256;
    int nblocks = (N + SCAN_B - 1) / SCAN_B;
    int cgrid = (N * 64 + 255) / 256;
    int ggrid = 148;
    int agrid = (N + 7) / 8;
    int ogrid = (int)(((long long)N * 32 + 255) / 256);

    // One-time prep: fp16 mirror of x, W fragments, CSR build
    convert_x<<<cgrid, 256>>>((const float2*)x, xh, N * 64);
    prep_w<<<64, 256>>>(W1l, W1r, Whl, Whr);
    cudaMemsetAsync(deg, 0, (size_t)N * sizeof(int), 0);
    hist_k<<<egrid, 256>>>(ei, E, deg);
    scan1_k<<<nblocks, SCAN_B>>>(deg, N, tmp, psum);
    scan2_k<<<1, SCAN_B>>>(psum, nblocks);
    scan3_k<<<nblocks, SCAN_B>>>(tmp, psum, N, E, rowptr, cursor);
    fill_k<<<egrid, 256>>>(ei, E, cursor, esrc);

    // Layer 1
    gather_k<<<agrid, 256>>>((const uint2*)xh, rowptr, esrc, s, N);
    sage_bf16<0><<<ggrid, THREADS, SMEM_TOTAL_BYTES>>>(x, (const float*)s,
                                                       wfrag, b1l, (float*)h1, h1h, N);

    // Layer 2
    gather_k<<<agrid, 256>>>((const uint2*)h1h, rowptr, esrc, s, N);
    sage_bf16<1><<<ggrid, THREADS, SMEM_TOTAL_BYTES>>>((const float*)h1, (const float*)s,
                                                       wfrag + 8192, bhl, (float*)h2, h2h, N);

    // Layer 3
    gather_k<<<agrid, 256>>>((const uint2*)h2h, rowptr, esrc, s, N);
    sage_out_k<<<ogrid, 256>>>((const float*)h2, (const float*)s,
                               W2l, b2l, W2r, out, N);
}

// round 12
// speedup vs baseline: 1.1386x; 1.1386x over previous
#include <cuda_runtime.h>
#include <math.h>

#define DHH 128
#define NMAX 50000
#define EMAX 800000
#define MT 64            // nodes per C tile
#define NTILES 16        // 16 n-tiles of 8 = 128 output feats
#define KST 16           // K-steps of 16 over fused K=256
#define THREADS 512
#define A_STRIDE 132                               // 128 k-pairs + 4 pad
#define SMEM_W_BYTES (KST * NTILES * 32 * 16)      // 8192 uint4 = 131072
#define SMEM_A_UINTS (MT * A_STRIDE)               // 8448
#define SMEM_TOTAL_BYTES (SMEM_W_BYTES + 2 * SMEM_A_UINTS * 4)

// Scratch (allocation-free: static device globals)
__device__ __align__(16) float4 g_s [NMAX * DHH / 4];
__device__ __align__(16) float4 g_h1[NMAX * DHH / 4];
__device__ __align__(16) float4 g_h2[NMAX * DHH / 4];
__device__ __align__(16) uint4 g_wfrag[2 * 8192];  // pre-split W fragments
__device__ int g_deg[NMAX];
__device__ int g_start[NMAX];
__device__ int g_cursor[NMAX];
__device__ int g_esrc[EMAX];
__device__ int g_alloc_ctr;

// ---------------------------------------------------------------------------
// bf16 split helpers
// ---------------------------------------------------------------------------
__device__ __forceinline__ unsigned pack_bf16x2(float lo, float hi) {
    unsigned u;
    asm("cvt.rn.bf16x2.f32 %0, %1, %2;" : "=r"(u) : "f"(hi), "f"(lo));
    return u;
}

__device__ __forceinline__ void split2(float x, float y, unsigned& hi, unsigned& lo) {
    hi = pack_bf16x2(x, y);
    float xh = __uint_as_float(hi << 16);
    float yh = __uint_as_float(hi & 0xffff0000u);
    lo = pack_bf16x2(x - xh, y - yh);
}

__device__ __forceinline__ void mma16(float* c, const unsigned* a, unsigned b0, unsigned b1) {
    asm volatile("mma.sync.aligned.m16n8k16.row.col.f32.bf16.bf16.f32 "
        "{%0,%1,%2,%3}, {%4,%5,%6,%7}, {%8,%9}, {%0,%1,%2,%3};"
        : "+f"(c[0]), "+f"(c[1]), "+f"(c[2]), "+f"(c[3])
        : "r"(a[0]), "r"(a[1]), "r"(a[2]), "r"(a[3]), "r"(b0), "r"(b1));
}

// ---------------------------------------------------------------------------
// Prep: split W into bf16 hi/lo fragment order (see layout comment R4).
// ---------------------------------------------------------------------------
__global__ void prep_w(const float* __restrict__ W1l, const float* __restrict__ W1r,
                       const float* __restrict__ Whl, const float* __restrict__ Whr) {
    int idx = blockIdx.x * blockDim.x + threadIdx.x;
    if (idx >= 16384) return;
    int layer = idx >> 13;
    int rem = idx & 8191;
    int S = rem >> 9;
    int T = (rem >> 5) & 15;
    int lane = rem & 31;
    const float* W = (S < 8) ? (layer ? Whl : W1l) : (layer ? Whr : W1r);
    int k0 = (S & 7) * 16;
    int row = T * 8 + (lane >> 2);
    int cc = lane & 3;
    const float* p = W + row * DHH + k0 + 2 * cc;
    unsigned h0, l0, h1, l1;
    split2(__ldg(&p[0]), __ldg(&p[1]), h0, l0);
    split2(__ldg(&p[8]), __ldg(&p[9]), h1, l1);
    g_wfrag[idx] = make_uint4(h0, h1, l0, l1);
}

// ---------------------------------------------------------------------------
// CSR build: histogram -> warp-aggregated range allocation -> fill.
// Node ranges need not be ordered; each node just needs a private contiguous
// slice of esrc.
// ---------------------------------------------------------------------------
__global__ void hist_k(const int* __restrict__ ei, int E, int* __restrict__ deg) {
    int e = blockIdx.x * blockDim.x + threadIdx.x;
    if (e == 0) g_alloc_ctr = 0;   // nothing reads it until alloc_k
    if (e < E) atomicAdd(&deg[ei[E + e]], 1);
}

__global__ void alloc_k(const int* __restrict__ deg, int N,
                        int* __restrict__ start, int* __restrict__ cursor) {
    int i = blockIdx.x * blockDim.x + threadIdx.x;
    int lane = threadIdx.x & 31;
    int d = (i < N) ? deg[i] : 0;
    // inclusive warp scan of d
    int pref = d;
    #pragma unroll
    for (int off = 1; off < 32; off <<= 1) {
        int v = __shfl_up_sync(0xffffffff, pref, off);
        if (lane >= off) pref += v;
    }
    int total = __shfl_sync(0xffffffff, pref, 31);
    int base = 0;
    if (lane == 31) base = atomicAdd(&g_alloc_ctr, total);
    base = __shfl_sync(0xffffffff, base, 31);
    int mybase = base + pref - d;
    if (i < N) {
        start[i] = mybase;
        cursor[i] = mybase;
    }
}

__global__ void fill_k(const int* __restrict__ ei, int E,
                       int* __restrict__ cursor, int* __restrict__ esrc) {
    int e = blockIdx.x * blockDim.x + threadIdx.x;
    if (e < E) {
        int dst = ei[E + e];
        int p = atomicAdd(&cursor[dst], 1);
        esrc[p] = ei[e];
    }
}

// ---------------------------------------------------------------------------
// Gather: one warp per dst node, atomic-free mean aggregation, 8-deep MLP.
// ---------------------------------------------------------------------------
__global__ void gather_k(const float4* __restrict__ feat, const int* __restrict__ start,
                         const int* __restrict__ deg, const int* __restrict__ esrc,
                         float4* __restrict__ s, int N) {
    int n = blockIdx.x * 8 + (threadIdx.x >> 5);
    if (n >= N) return;
    int lane = threadIdx.x & 31;
    int beg = __ldg(&start[n]);
    int d = __ldg(&deg[n]);
    int end = beg + d;

    float4 a0 = make_float4(0.f, 0.f, 0.f, 0.f);
    float4 a1 = make_float4(0.f, 0.f, 0.f, 0.f);
    float4 a2 = make_float4(0.f, 0.f, 0.f, 0.f);
    float4 a3 = make_float4(0.f, 0.f, 0.f, 0.f);

    int e = beg;
    for (; e + 8 <= end; e += 8) {
        int s0 = __ldg(&esrc[e]),     s1 = __ldg(&esrc[e + 1]);
        int s2 = __ldg(&esrc[e + 2]), s3 = __ldg(&esrc[e + 3]);
        int s4 = __ldg(&esrc[e + 4]), s5 = __ldg(&esrc[e + 5]);
        int s6 = __ldg(&esrc[e + 6]), s7 = __ldg(&esrc[e + 7]);
        float4 v0 = __ldg(&feat[(long long)s0 * 32 + lane]);
        float4 v1 = __ldg(&feat[(long long)s1 * 32 + lane]);
        float4 v2 = __ldg(&feat[(long long)s2 * 32 + lane]);
        float4 v3 = __ldg(&feat[(long long)s3 * 32 + lane]);
        float4 v4 = __ldg(&feat[(long long)s4 * 32 + lane]);
        float4 v5 = __ldg(&feat[(long long)s5 * 32 + lane]);
        float4 v6 = __ldg(&feat[(long long)s6 * 32 + lane]);
        float4 v7 = __ldg(&feat[(long long)s7 * 32 + lane]);
        a0.x += v0.x; a0.y += v0.y; a0.z += v0.z; a0.w += v0.w;
        a1.x += v1.x; a1.y += v1.y; a1.z += v1.z; a1.w += v1.w;
        a2.x += v2.x; a2.y += v2.y; a2.z += v2.z; a2.w += v2.w;
        a3.x += v3.x; a3.y += v3.y; a3.z += v3.z; a3.w += v3.w;
        a0.x += v4.x; a0.y += v4.y; a0.z += v4.z; a0.w += v4.w;
        a1.x += v5.x; a1.y += v5.y; a1.z += v5.z; a1.w += v5.w;
        a2.x += v6.x; a2.y += v6.y; a2.z += v6.z; a2.w += v6.w;
        a3.x += v7.x; a3.y += v7.y; a3.z += v7.z; a3.w += v7.w;
    }
    for (; e + 4 <= end; e += 4) {
        int s0 = __ldg(&esrc[e]),     s1 = __ldg(&esrc[e + 1]);
        int s2 = __ldg(&esrc[e + 2]), s3 = __ldg(&esrc[e + 3]);
        float4 v0 = __ldg(&feat[(long long)s0 * 32 + lane]);
        float4 v1 = __ldg(&feat[(long long)s1 * 32 + lane]);
        float4 v2 = __ldg(&feat[(long long)s2 * 32 + lane]);
        float4 v3 = __ldg(&feat[(long long)s3 * 32 + lane]);
        a0.x += v0.x; a0.y += v0.y; a0.z += v0.z; a0.w += v0.w;
        a1.x += v1.x; a1.y += v1.y; a1.z += v1.z; a1.w += v1.w;
        a2.x += v2.x; a2.y += v2.y; a2.z += v2.z; a2.w += v2.w;
        a3.x += v3.x; a3.y += v3.y; a3.z += v3.z; a3.w += v3.w;
    }
    for (; e < end; e++) {
        int s0 = __ldg(&esrc[e]);
        float4 v0 = __ldg(&feat[(long long)s0 * 32 + lane]);
        a0.x += v0.x; a0.y += v0.y; a0.z += v0.z; a0.w += v0.w;
    }

    float inv = 1.0f / fmaxf((float)d, 1.0f);
    float4 r;
    r.x = (a0.x + a1.x + a2.x + a3.x) * inv;
    r.y = (a0.y + a1.y + a2.y + a3.y) * inv;
    r.z = (a0.z + a1.z + a2.z + a3.z) * inv;
    r.w = (a0.w + a1.w + a2.w + a3.w) * inv;
    s[(long long)n * 32 + lane] = r;
}

// ---------------------------------------------------------------------------
// Fused SAGE layer: C = act([agg | x] . [Wl|Wr]^T + bl), split-bf16 mma.
// ---------------------------------------------------------------------------
template <int ACT>
__global__ __launch_bounds__(THREADS, 1)
void sage_bf16(const float* __restrict__ x, const float* __restrict__ s,
               const uint4* __restrict__ wfrag, const float* __restrict__ bl,
               float* __restrict__ out, int N) {
    extern __shared__ char smemraw[];
    uint4*    shW  = (uint4*)smemraw;                       // [KST*NTILES*32]
    unsigned* shAh = (unsigned*)(smemraw + SMEM_W_BYTES);   // [MT][A_STRIDE]
    unsigned* shAl = shAh + SMEM_A_UINTS;

    int t = threadIdx.x;
    int w = t >> 5, lane = t & 31;
    int r = lane >> 2, c = lane & 3;
    int g = w >> 2;        // row-group 0..3
    int q = w & 3;         // tile quarter 0..3
    int mbase = g * 16;

    #pragma unroll
    for (int i = 0; i < 16; i++)
        shW[t + i * THREADS] = __ldg(&wfrag[t + i * THREADS]);

    float bias0[4], bias1[4];
    #pragma unroll
    for (int i = 0; i < 4; i++) {
        int colg = (q * 4 + i) * 8 + 2 * c;
        bias0[i] = __ldg(&bl[colg]);
        bias1[i] = __ldg(&bl[colg + 1]);
    }

    int mtiles = (N + MT - 1) / MT;
    for (int tile = blockIdx.x; tile < mtiles; tile += gridDim.x) {
        __syncthreads();
        int n0 = tile * MT;

        #pragma unroll
        for (int i = 0; i < 8; i++) {
            int flat = t + i * THREADS;
            int row = flat >> 6;
            int c4 = flat & 63;
            int node = n0 + row;
            float4 v = make_float4(0.f, 0.f, 0.f, 0.f);
            if (node < N) {
                if (c4 < 32)
                    v = __ldg((const float4*)s + (long long)node * 32 + c4);
                else
                    v = __ldg((const float4*)x + (long long)node * 32 + (c4 - 32));
            }
            unsigned h01, l01, h23, l23;
            split2(v.x, v.y, h01, l01);
            split2(v.z, v.w, h23, l23);
            int base = row * A_STRIDE + c4 * 2;
            *(uint2*)&shAh[base] = make_uint2(h01, h23);
            *(uint2*)&shAl[base] = make_uint2(l01, l23);
        }
        __syncthreads();

        float acc[4][4];
        #pragma unroll
        for (int T = 0; T < 4; T++)
            acc[T][0] = acc[T][1] = acc[T][2] = acc[T][3] = 0.f;

        #pragma unroll 4
        for (int S = 0; S < KST; S++) {
            int ra = (mbase + r) * A_STRIDE + S * 8 + c;
            int rb = (mbase + r + 8) * A_STRIDE + S * 8 + c;
            unsigned ah[4], al[4];
            ah[0] = shAh[ra]; ah[1] = shAh[rb]; ah[2] = shAh[ra + 4]; ah[3] = shAh[rb + 4];
            al[0] = shAl[ra]; al[1] = shAl[rb]; al[2] = shAl[ra + 4]; al[3] = shAl[rb + 4];
            #pragma unroll
            for (int T = 0; T < 4; T++) {
                uint4 b = shW[(S * NTILES + q * 4 + T) * 32 + lane];
                mma16(acc[T], al, b.x, b.y);   // al*bh
                mma16(acc[T], ah, b.z, b.w);   // ah*bl
                mma16(acc[T], ah, b.x, b.y);   // ah*bh
            }
        }

        #pragma unroll
        for (int T = 0; T < 4; T++) {
            int colg = (q * 4 + T) * 8 + 2 * c;
            float v0 = acc[T][0] + bias0[T], v1 = acc[T][1] + bias1[T];
            float v2 = acc[T][2] + bias0[T], v3 = acc[T][3] + bias1[T];
            if (ACT == 0) {
                v0 = fmaxf(v0, 0.f); v1 = fmaxf(v1, 0.f);
                v2 = fmaxf(v2, 0.f); v3 = fmaxf(v3, 0.f);
            } else {
                v0 = (v0 > 0.f) ? v0 : expm1f(v0);
                v1 = (v1 > 0.f) ? v1 : expm1f(v1);
                v2 = (v2 > 0.f) ? v2 : expm1f(v2);
                v3 = (v3 > 0.f) ? v3 : expm1f(v3);
            }
            int node0 = n0 + mbase + r;
            if (node0 < N)
                *(float2*)&out[(long long)node0 * DHH + colg] = make_float2(v0, v1);
            if (node0 + 8 < N)
                *(float2*)&out[(long long)(node0 + 8) * DHH + colg] = make_float2(v2, v3);
        }
    }
}

// ---------------------------------------------------------------------------
// Output layer (DOUT=8) + log_softmax. One warp per node. s is already mean.
// ---------------------------------------------------------------------------
__global__ void sage_out_k(const float* __restrict__ x, const float* __restrict__ s,
                           const float* __restrict__ Wl, const float* __restrict__ bl,
                           const float* __restrict__ Wr,
                           float* __restrict__ out, int N) {
    long long tid = (long long)blockIdx.x * blockDim.x + threadIdx.x;
    int n = (int)(tid >> 5);
    if (n >= N) return;
    int lane = (int)(tid & 31);

    float acc[8];
    #pragma unroll
    for (int j = 0; j < 8; j++) acc[j] = 0.0f;

    #pragma unroll
    for (int ch = 0; ch < 4; ch++) {
        int k = lane + ch * 32;
        float sv = s[(long long)n * DHH + k];
        float xv = x[(long long)n * DHH + k];
        #pragma unroll
        for (int j = 0; j < 8; j++) {
            acc[j] = fmaf(sv, __ldg(&Wl[j * DHH + k]), acc[j]);
            acc[j] = fmaf(xv, __ldg(&Wr[j * DHH + k]), acc[j]);
        }
    }

    #pragma unroll
    for (int j = 0; j < 8; j++) {
        #pragma unroll
        for (int off = 16; off > 0; off >>= 1)
            acc[j] += __shfl_xor_sync(0xffffffff, acc[j], off);
    }

    if (lane == 0) {
        float h[8];
        float m = -1e30f;
        #pragma unroll
        for (int j = 0; j < 8; j++) {
            h[j] = acc[j] + bl[j];
            m = fmaxf(m, h[j]);
        }
        float sum = 0.0f;
        #pragma unroll
        for (int j = 0; j < 8; j++) sum += expf(h[j] - m);
        float lse = logf(sum) + m;
        #pragma unroll
        for (int j = 0; j < 8; j++) out[(long long)n * 8 + j] = h[j] - lse;
    }
}

// ---------------------------------------------------------------------------
extern "C" void kernel_launch(void* const* d_in, const int* in_sizes, int n_in,
                              void* d_out, int out_size) {
    const float* x   = (const float*)d_in[0];
    const int*   ei  = (const int*)d_in[1];
    // d_in[2] = edge_attr, unused
    const float* W1l = (const float*)d_in[3];
    const float* b1l = (const float*)d_in[4];
    const float* W1r = (const float*)d_in[5];
    const float* Whl = (const float*)d_in[6];
    const float* bhl = (const float*)d_in[7];
    const float* Whr = (const float*)d_in[8];
    const float* W2l = (const float*)d_in[9];
    const float* b2l = (const float*)d_in[10];
    const float* W2r = (const float*)d_in[11];
    float* out = (float*)d_out;

    int N = in_sizes[0] / DHH;
    int E = in_sizes[1] / 2;

    float4 *s, *h1, *h2;
    uint4* wfrag;
    int *deg, *start, *cursor, *esrc;
    cudaGetSymbolAddress((void**)&s, g_s);
    cudaGetSymbolAddress((void**)&h1, g_h1);
    cudaGetSymbolAddress((void**)&h2, g_h2);
    cudaGetSymbolAddress((void**)&wfrag, g_wfrag);
    cudaGetSymbolAddress((void**)&deg, g_deg);
    cudaGetSymbolAddress((void**)&start, g_start);
    cudaGetSymbolAddress((void**)&cursor, g_cursor);
    cudaGetSymbolAddress((void**)&esrc, g_esrc);

    cudaFuncSetAttribute(sage_bf16<0>, cudaFuncAttributeMaxDynamicSharedMemorySize,
                         SMEM_TOTAL_BYTES);
    cudaFuncSetAttribute(sage_bf16<1>, cudaFuncAttributeMaxDynamicSharedMemorySize,
                         SMEM_TOTAL_BYTES);

    int egrid = (E + 255) / 256;
    int ngrid = (N + 255) / 256;
    int ggrid = 148;
    int agrid = (N + 7) / 8;
    int ogrid = (int)(((long long)N * 32 + 255) / 256);

    // CSR build (also zeroes the alloc counter inside hist_k)
    cudaMemsetAsync(deg, 0, (size_t)N * sizeof(int), 0);
    hist_k<<<egrid, 256>>>(ei, E, deg);
    alloc_k<<<ngrid, 256>>>(deg, N, start, cursor);
    fill_k<<<egrid, 256>>>(ei, E, cursor, esrc);

    // Layer 1 (prep_w after the first gather so ncu's -s 5 capture lands on a
    // heavy kernel; prep_w only needs to finish before sage_bf16<0>)
    gather_k<<<agrid, 256>>>((const float4*)x, start, deg, esrc, s, N);
    prep_w<<<64, 256>>>(W1l, W1r, Whl, Whr);
    sage_bf16<0><<<ggrid, THREADS, SMEM_TOTAL_BYTES>>>(x, (const float*)s,
                                                       wfrag, b1l, (float*)h1, N);

    // Layer 2
    gather_k<<<agrid, 256>>>(h1, start, deg, esrc, s, N);
    sage_bf16<1><<<ggrid, THREADS, SMEM_TOTAL_BYTES>>>((const float*)h1, (const float*)s,
                                                       wfrag + 8192, bhl, (float*)h2, N);

    // Layer 3
    gather_k<<<agrid, 256>>>(h2, start, deg, esrc, s, N);
    sage_out_k<<<ogrid, 256>>>((const float*)h2, (const float*)s,
                               W2l, b2l, W2r, out, N);
}

// round 13
// speedup vs baseline: 1.2839x; 1.1276x over previous
#include <cuda_runtime.h>
#include <cuda_fp16.h>
#include <math.h>

#define DHH 128
#define NMAX 50000
#define EMAX 800000
#define MT 64            // nodes per C tile
#define NTILES 16        // 16 n-tiles of 8 = 128 output feats
#define KST 16           // K-steps of 16 over fused K=256
#define THREADS 512
#define A_STRIDE 132                               // 128 k-pairs + 4 pad
#define SMEM_W_BYTES (KST * NTILES * 32 * 16)      // 8192 uint4 = 131072
#define SMEM_A_UINTS (MT * A_STRIDE)               // 8448
#define SMEM_TOTAL_BYTES (SMEM_W_BYTES + 2 * SMEM_A_UINTS * 4)

// Scratch (allocation-free: static device globals).
// Node features x/h1/h2 stored fp16-packed: 64 uints (fp16x2) per node.
// Aggregated mean s stays f32.
__device__ __align__(16) float4 g_s [NMAX * DHH / 4];
__device__ __align__(16) unsigned g_xh [NMAX * 64];
__device__ __align__(16) unsigned g_h1h[NMAX * 64];
__device__ __align__(16) unsigned g_h2h[NMAX * 64];
__device__ __align__(16) uint4 g_wfrag[2 * 8192];  // pre-split W fragments
__device__ int g_deg[NMAX];
__device__ int g_start[NMAX];
__device__ int g_cursor[NMAX];
__device__ int g_esrc[EMAX];
__device__ int g_alloc_ctr;

// ---------------------------------------------------------------------------
// fp16 / bf16 helpers
// ---------------------------------------------------------------------------
__device__ __forceinline__ __half2 ash2(unsigned u) {
    return *reinterpret_cast<__half2*>(&u);
}
__device__ __forceinline__ unsigned packh2(float a, float b) {
    __half2 h = __floats2half2_rn(a, b);
    return *reinterpret_cast<unsigned*>(&h);
}
__device__ __forceinline__ float2 unpackh2(unsigned u) {
    return __half22float2(ash2(u));
}

__device__ __forceinline__ unsigned pack_bf16x2(float lo, float hi) {
    unsigned u;
    asm("cvt.rn.bf16x2.f32 %0, %1, %2;" : "=r"(u) : "f"(hi), "f"(lo));
    return u;
}

__device__ __forceinline__ void split2(float x, float y, unsigned& hi, unsigned& lo) {
    hi = pack_bf16x2(x, y);
    float xh = __uint_as_float(hi << 16);
    float yh = __uint_as_float(hi & 0xffff0000u);
    lo = pack_bf16x2(x - xh, y - yh);
}

__device__ __forceinline__ void mma16(float* c, const unsigned* a, unsigned b0, unsigned b1) {
    asm volatile("mma.sync.aligned.m16n8k16.row.col.f32.bf16.bf16.f32 "
        "{%0,%1,%2,%3}, {%4,%5,%6,%7}, {%8,%9}, {%0,%1,%2,%3};"
        : "+f"(c[0]), "+f"(c[1]), "+f"(c[2]), "+f"(c[3])
        : "r"(a[0]), "r"(a[1]), "r"(a[2]), "r"(a[3]), "r"(b0), "r"(b1));
}

// ---------------------------------------------------------------------------
// Convert x (f32) -> fp16
// ---------------------------------------------------------------------------
__global__ void convert_x(const float2* __restrict__ x, unsigned* __restrict__ xh, int n) {
    int i = blockIdx.x * blockDim.x + threadIdx.x;
    if (i < n) {
        float2 v = __ldg(&x[i]);
        xh[i] = packh2(v.x, v.y);
    }
}

// ---------------------------------------------------------------------------
// Prep: split W into bf16 hi/lo fragment order (see layout comment R4).
// ---------------------------------------------------------------------------
__global__ void prep_w(const float* __restrict__ W1l, const float* __restrict__ W1r,
                       const float* __restrict__ Whl, const float* __restrict__ Whr) {
    int idx = blockIdx.x * blockDim.x + threadIdx.x;
    if (idx >= 16384) return;
    int layer = idx >> 13;
    int rem = idx & 8191;
    int S = rem >> 9;
    int T = (rem >> 5) & 15;
    int lane = rem & 31;
    const float* W = (S < 8) ? (layer ? Whl : W1l) : (layer ? Whr : W1r);
    int k0 = (S & 7) * 16;
    int row = T * 8 + (lane >> 2);
    int cc = lane & 3;
    const float* p = W + row * DHH + k0 + 2 * cc;
    unsigned h0, l0, h1, l1;
    split2(__ldg(&p[0]), __ldg(&p[1]), h0, l0);
    split2(__ldg(&p[8]), __ldg(&p[9]), h1, l1);
    g_wfrag[idx] = make_uint4(h0, h1, l0, l1);
}

// ---------------------------------------------------------------------------
// CSR build: histogram -> warp-aggregated range allocation -> fill.
// ---------------------------------------------------------------------------
__global__ void hist_k(const int* __restrict__ ei, int E, int* __restrict__ deg) {
    int e = blockIdx.x * blockDim.x + threadIdx.x;
    if (e == 0) g_alloc_ctr = 0;   // nothing reads it until alloc_k
    if (e < E) atomicAdd(&deg[ei[E + e]], 1);
}

__global__ void alloc_k(const int* __restrict__ deg, int N,
                        int* __restrict__ start, int* __restrict__ cursor) {
    int i = blockIdx.x * blockDim.x + threadIdx.x;
    int lane = threadIdx.x & 31;
    int d = (i < N) ? deg[i] : 0;
    int pref = d;
    #pragma unroll
    for (int off = 1; off < 32; off <<= 1) {
        int v = __shfl_up_sync(0xffffffff, pref, off);
        if (lane >= off) pref += v;
    }
    int total = __shfl_sync(0xffffffff, pref, 31);
    int base = 0;
    if (lane == 31) base = atomicAdd(&g_alloc_ctr, total);
    base = __shfl_sync(0xffffffff, base, 31);
    int mybase = base + pref - d;
    if (i < N) {
        start[i] = mybase;
        cursor[i] = mybase;
    }
}

__global__ void fill_k(const int* __restrict__ ei, int E,
                       int* __restrict__ cursor, int* __restrict__ esrc) {
    int e = blockIdx.x * blockDim.x + threadIdx.x;
    if (e < E) {
        int dst = ei[E + e];
        int p = atomicAdd(&cursor[dst], 1);
        esrc[p] = ei[e];
    }
}

// ---------------------------------------------------------------------------
// Gather: one warp per dst node. fp16 feature reads (half the L2 bytes),
// HADD2 partial sums over 4-edge groups, f32 master accumulator, f32 output.
// Lane owns feats [4*lane .. 4*lane+3] = one uint2.
// ---------------------------------------------------------------------------
__global__ void gather_k(const uint2* __restrict__ feath, const int* __restrict__ start,
                         const int* __restrict__ deg, const int* __restrict__ esrc,
                         float4* __restrict__ s, int N) {
    int n = blockIdx.x * 8 + (threadIdx.x >> 5);
    if (n >= N) return;
    int lane = threadIdx.x & 31;
    int beg = __ldg(&start[n]);
    int d = __ldg(&deg[n]);
    int end = beg + d;

    float4 acc = make_float4(0.f, 0.f, 0.f, 0.f);

    int e = beg;
    for (; e + 8 <= end; e += 8) {
        int s0 = __ldg(&esrc[e]),     s1 = __ldg(&esrc[e + 1]);
        int s2 = __ldg(&esrc[e + 2]), s3 = __ldg(&esrc[e + 3]);
        int s4 = __ldg(&esrc[e + 4]), s5 = __ldg(&esrc[e + 5]);
        int s6 = __ldg(&esrc[e + 6]), s7 = __ldg(&esrc[e + 7]);
        uint2 u0 = __ldg(&feath[(long long)s0 * 32 + lane]);
        uint2 u1 = __ldg(&feath[(long long)s1 * 32 + lane]);
        uint2 u2 = __ldg(&feath[(long long)s2 * 32 + lane]);
        uint2 u3 = __ldg(&feath[(long long)s3 * 32 + lane]);
        uint2 u4 = __ldg(&feath[(long long)s4 * 32 + lane]);
        uint2 u5 = __ldg(&feath[(long long)s5 * 32 + lane]);
        uint2 u6 = __ldg(&feath[(long long)s6 * 32 + lane]);
        uint2 u7 = __ldg(&feath[(long long)s7 * 32 + lane]);
        // group A: edges 0-3
        __half2 pa0 = __hadd2(ash2(u0.x), ash2(u1.x));
        __half2 pa1 = __hadd2(ash2(u0.y), ash2(u1.y));
        __half2 qa0 = __hadd2(ash2(u2.x), ash2(u3.x));
        __half2 qa1 = __hadd2(ash2(u2.y), ash2(u3.y));
        pa0 = __hadd2(pa0, qa0); pa1 = __hadd2(pa1, qa1);
        float2 fa0 = __half22float2(pa0), fa1 = __half22float2(pa1);
        acc.x += fa0.x; acc.y += fa0.y; acc.z += fa1.x; acc.w += fa1.y;
        // group B: edges 4-7
        __half2 pb0 = __hadd2(ash2(u4.x), ash2(u5.x));
        __half2 pb1 = __hadd2(ash2(u4.y), ash2(u5.y));
        __half2 qb0 = __hadd2(ash2(u6.x), ash2(u7.x));
        __half2 qb1 = __hadd2(ash2(u6.y), ash2(u7.y));
        pb0 = __hadd2(pb0, qb0); pb1 = __hadd2(pb1, qb1);
        float2 fb0 = __half22float2(pb0), fb1 = __half22float2(pb1);
        acc.x += fb0.x; acc.y += fb0.y; acc.z += fb1.x; acc.w += fb1.y;
    }
    for (; e + 4 <= end; e += 4) {
        int s0 = __ldg(&esrc[e]),     s1 = __ldg(&esrc[e + 1]);
        int s2 = __ldg(&esrc[e + 2]), s3 = __ldg(&esrc[e + 3]);
        uint2 u0 = __ldg(&feath[(long long)s0 * 32 + lane]);
        uint2 u1 = __ldg(&feath[(long long)s1 * 32 + lane]);
        uint2 u2 = __ldg(&feath[(long long)s2 * 32 + lane]);
        uint2 u3 = __ldg(&feath[(long long)s3 * 32 + lane]);
        __half2 p0 = __hadd2(ash2(u0.x), ash2(u1.x));
        __half2 p1 = __hadd2(ash2(u0.y), ash2(u1.y));
        __half2 q0 = __hadd2(ash2(u2.x), ash2(u3.x));
        __half2 q1 = __hadd2(ash2(u2.y), ash2(u3.y));
        p0 = __hadd2(p0, q0); p1 = __hadd2(p1, q1);
        float2 f0 = __half22float2(p0), f1 = __half22float2(p1);
        acc.x += f0.x; acc.y += f0.y; acc.z += f1.x; acc.w += f1.y;
    }
    for (; e < end; e++) {
        int s0 = __ldg(&esrc[e]);
        uint2 u0 = __ldg(&feath[(long long)s0 * 32 + lane]);
        float2 f0 = unpackh2(u0.x), f1 = unpackh2(u0.y);
        acc.x += f0.x; acc.y += f0.y; acc.z += f1.x; acc.w += f1.y;
    }

    float inv = 1.0f / fmaxf((float)d, 1.0f);
    float4 r = make_float4(acc.x * inv, acc.y * inv, acc.z * inv, acc.w * inv);
    s[(long long)n * 32 + lane] = r;
}

// ---------------------------------------------------------------------------
// Fused SAGE layer: C = act([agg | x] . [Wl|Wr]^T + bl), split-bf16 mma.
// s input f32, x input fp16-packed; output fp16-packed.
// ---------------------------------------------------------------------------
template <int ACT>
__global__ __launch_bounds__(THREADS, 1)
void sage_bf16(const uint2* __restrict__ xh, const float* __restrict__ s,
               const uint4* __restrict__ wfrag, const float* __restrict__ bl,
               unsigned* __restrict__ outh, int N) {
    extern __shared__ char smemraw[];
    uint4*    shW  = (uint4*)smemraw;                       // [KST*NTILES*32]
    unsigned* shAh = (unsigned*)(smemraw + SMEM_W_BYTES);   // [MT][A_STRIDE]
    unsigned* shAl = shAh + SMEM_A_UINTS;

    int t = threadIdx.x;
    int w = t >> 5, lane = t & 31;
    int r = lane >> 2, c = lane & 3;
    int g = w >> 2;        // row-group 0..3
    int q = w & 3;         // tile quarter 0..3
    int mbase = g * 16;

    #pragma unroll
    for (int i = 0; i < 16; i++)
        shW[t + i * THREADS] = __ldg(&wfrag[t + i * THREADS]);

    float bias0[4], bias1[4];
    #pragma unroll
    for (int i = 0; i < 4; i++) {
        int colg = (q * 4 + i) * 8 + 2 * c;
        bias0[i] = __ldg(&bl[colg]);
        bias1[i] = __ldg(&bl[colg + 1]);
    }

    int mtiles = (N + MT - 1) / MT;
    for (int tile = blockIdx.x; tile < mtiles; tile += gridDim.x) {
        __syncthreads();
        int n0 = tile * MT;

        #pragma unroll
        for (int i = 0; i < 8; i++) {
            int flat = t + i * THREADS;
            int row = flat >> 6;
            int c4 = flat & 63;
            int node = n0 + row;
            float4 v = make_float4(0.f, 0.f, 0.f, 0.f);
            if (node < N) {
                if (c4 < 32) {
                    v = __ldg((const float4*)s + (long long)node * 32 + c4);
                } else {
                    uint2 u = __ldg(&xh[(long long)node * 32 + (c4 - 32)]);
                    float2 a = unpackh2(u.x), b = unpackh2(u.y);
                    v = make_float4(a.x, a.y, b.x, b.y);
                }
            }
            unsigned h01, l01, h23, l23;
            split2(v.x, v.y, h01, l01);
            split2(v.z, v.w, h23, l23);
            int base = row * A_STRIDE + c4 * 2;
            *(uint2*)&shAh[base] = make_uint2(h01, h23);
            *(uint2*)&shAl[base] = make_uint2(l01, l23);
        }
        __syncthreads();

        float acc[4][4];
        #pragma unroll
        for (int T = 0; T < 4; T++)
            acc[T][0] = acc[T][1] = acc[T][2] = acc[T][3] = 0.f;

        #pragma unroll 4
        for (int S = 0; S < KST; S++) {
            int ra = (mbase + r) * A_STRIDE + S * 8 + c;
            int rb = (mbase + r + 8) * A_STRIDE + S * 8 + c;
            unsigned ah[4], al[4];
            ah[0] = shAh[ra]; ah[1] = shAh[rb]; ah[2] = shAh[ra + 4]; ah[3] = shAh[rb + 4];
            al[0] = shAl[ra]; al[1] = shAl[rb]; al[2] = shAl[ra + 4]; al[3] = shAl[rb + 4];
            #pragma unroll
            for (int T = 0; T < 4; T++) {
                uint4 b = shW[(S * NTILES + q * 4 + T) * 32 + lane];
                mma16(acc[T], al, b.x, b.y);   // al*bh
                mma16(acc[T], ah, b.z, b.w);   // ah*bl
                mma16(acc[T], ah, b.x, b.y);   // ah*bh
            }
        }

        #pragma unroll
        for (int T = 0; T < 4; T++) {
            int colg = (q * 4 + T) * 8 + 2 * c;
            float v0 = acc[T][0] + bias0[T], v1 = acc[T][1] + bias1[T];
            float v2 = acc[T][2] + bias0[T], v3 = acc[T][3] + bias1[T];
            if (ACT == 0) {
                v0 = fmaxf(v0, 0.f); v1 = fmaxf(v1, 0.f);
                v2 = fmaxf(v2, 0.f); v3 = fmaxf(v3, 0.f);
            } else {
                v0 = (v0 > 0.f) ? v0 : expm1f(v0);
                v1 = (v1 > 0.f) ? v1 : expm1f(v1);
                v2 = (v2 > 0.f) ? v2 : expm1f(v2);
                v3 = (v3 > 0.f) ? v3 : expm1f(v3);
            }
            int node0 = n0 + mbase + r;
            int cw = colg >> 1;                 // uint word index within row
            if (node0 < N)
                outh[(long long)node0 * 64 + cw] = packh2(v0, v1);
            if (node0 + 8 < N)
                outh[(long long)(node0 + 8) * 64 + cw] = packh2(v2, v3);
        }
    }
}

// ---------------------------------------------------------------------------
// Output layer (DOUT=8) + log_softmax. One warp per node.
// Lane owns feats [4*lane..4*lane+3]; weights via vector LDG.128 (coalesced).
// ---------------------------------------------------------------------------
__global__ void sage_out_k(const uint2* __restrict__ xh, const float4* __restrict__ s,
                           const float* __restrict__ Wl, const float* __restrict__ bl,
                           const float* __restrict__ Wr,
                           float* __restrict__ out, int N) {
    long long tid = (long long)blockIdx.x * blockDim.x + threadIdx.x;
    int n = (int)(tid >> 5);
    if (n >= N) return;
    int lane = (int)(tid & 31);

    float4 sv = __ldg(&s[(long long)n * 32 + lane]);
    uint2 xu = __ldg(&xh[(long long)n * 32 + lane]);
    float2 x01 = unpackh2(xu.x), x23 = unpackh2(xu.y);

    float acc[8];
    #pragma unroll
    for (int j = 0; j < 8; j++) {
        float4 wl = __ldg((const float4*)(Wl + j * DHH) + lane);
        float4 wr = __ldg((const float4*)(Wr + j * DHH) + lane);
        acc[j] = sv.x * wl.x + sv.y * wl.y + sv.z * wl.z + sv.w * wl.w
               + x01.x * wr.x + x01.y * wr.y + x23.x * wr.z + x23.y * wr.w;
    }

    #pragma unroll
    for (int j = 0; j < 8; j++) {
        #pragma unroll
        for (int off = 16; off > 0; off >>= 1)
            acc[j] += __shfl_xor_sync(0xffffffff, acc[j], off);
    }

    if (lane == 0) {
        float h[8];
        float m = -1e30f;
        #pragma unroll
        for (int j = 0; j < 8; j++) {
            h[j] = acc[j] + bl[j];
            m = fmaxf(m, h[j]);
        }
        float sum = 0.0f;
        #pragma unroll
        for (int j = 0; j < 8; j++) sum += expf(h[j] - m);
        float lse = logf(sum) + m;
        #pragma unroll
        for (int j = 0; j < 8; j++) out[(long long)n * 8 + j] = h[j] - lse;
    }
}

// ---------------------------------------------------------------------------
extern "C" void kernel_launch(void* const* d_in, const int* in_sizes, int n_in,
                              void* d_out, int out_size) {
    const float* x   = (const float*)d_in[0];
    const int*   ei  = (const int*)d_in[1];
    // d_in[2] = edge_attr, unused
    const float* W1l = (const float*)d_in[3];
    const float* b1l = (const float*)d_in[4];
    const float* W1r = (const float*)d_in[5];
    const float* Whl = (const float*)d_in[6];
    const float* bhl = (const float*)d_in[7];
    const float* Whr = (const float*)d_in[8];
    const float* W2l = (const float*)d_in[9];
    const float* b2l = (const float*)d_in[10];
    const float* W2r = (const float*)d_in[11];
    float* out = (float*)d_out;

    int N = in_sizes[0] / DHH;
    int E = in_sizes[1] / 2;

    float4* s;
    unsigned *xh, *h1h, *h2h;
    uint4* wfrag;
    int *deg, *start, *cursor, *esrc;
    cudaGetSymbolAddress((void**)&s, g_s);
    cudaGetSymbolAddress((void**)&xh, g_xh);
    cudaGetSymbolAddress((void**)&h1h, g_h1h);
    cudaGetSymbolAddress((void**)&h2h, g_h2h);
    cudaGetSymbolAddress((void**)&wfrag, g_wfrag);
    cudaGetSymbolAddress((void**)&deg, g_deg);
    cudaGetSymbolAddress((void**)&start, g_start);
    cudaGetSymbolAddress((void**)&cursor, g_cursor);
    cudaGetSymbolAddress((void**)&esrc, g_esrc);

    cudaFuncSetAttribute(sage_bf16<0>, cudaFuncAttributeMaxDynamicSharedMemorySize,
                         SMEM_TOTAL_BYTES);
    cudaFuncSetAttribute(sage_bf16<1>, cudaFuncAttributeMaxDynamicSharedMemorySize,
                         SMEM_TOTAL_BYTES);

    int egrid = (E + 255) / 256;
    int ngrid = (N + 255) / 256;
    int cgrid = (N * 64 + 255) / 256;
    int ggrid = 148;
    int agrid = (N + 7) / 8;
    int ogrid = (int)(((long long)N * 32 + 255) / 256);

    // CSR build + fp16 conversion of x
    cudaMemsetAsync(deg, 0, (size_t)N * sizeof(int), 0);
    convert_x<<<cgrid, 256>>>((const float2*)x, xh, N * 64);
    hist_k<<<egrid, 256>>>(ei, E, deg);
    alloc_k<<<ngrid, 256>>>(deg, N, start, cursor);
    fill_k<<<egrid, 256>>>(ei, E, cursor, esrc);

    // Layer 1 (prep_w needs to finish only before sage_bf16<0>)
    gather_k<<<agrid, 256>>>((const uint2*)xh, start, deg, esrc, s, N);
    prep_w<<<64, 256>>>(W1l, W1r, Whl, Whr);
    sage_bf16<0><<<ggrid, THREADS, SMEM_TOTAL_BYTES>>>((const uint2*)xh, (const float*)s,
                                                       wfrag, b1l, h1h, N);

    // Layer 2
    gather_k<<<agrid, 256>>>((const uint2*)h1h, start, deg, esrc, s, N);
    sage_bf16<1><<<ggrid, THREADS, SMEM_TOTAL_BYTES>>>((const uint2*)h1h, (const float*)s,
                                                       wfrag + 8192, bhl, h2h, N);

    // Layer 3
    gather_k<<<agrid, 256>>>((const uint2*)h2h, start, deg, esrc, s, N);
    sage_out_k<<<ogrid, 256>>>((const uint2*)h2h, s, W2l, b2l, W2r, out, N);
}

// round 15
// speedup vs baseline: 1.3032x; 1.0151x over previous
#include <cuda_runtime.h>
#include <cuda_fp16.h>
#include <math.h>

#define DHH 128
#define NMAX 50000
#define EMAX 800000
#define MT 64            // nodes per C tile
#define NTILES 16        // 16 n-tiles of 8 = 128 output feats
#define KST 16           // K-steps of 16 over fused K=256
#define THREADS_G 1024   // GEMM block: 32 warps
#define A_STRIDE 132                               // 128 k-pairs + 4 pad
#define SMEM_W_BYTES (KST * NTILES * 32 * 16)      // 8192 uint4 = 131072
#define SMEM_A_UINTS (MT * A_STRIDE)               // 8448
#define SMEM_TOTAL_BYTES (SMEM_W_BYTES + 2 * SMEM_A_UINTS * 4)

// Scratch (allocation-free: static device globals).
// Node features x/h1/h2 stored fp16-packed: 64 uints (fp16x2) per node.
// Aggregated mean s stays f32.
__device__ __align__(16) float4 g_s [NMAX * DHH / 4];
__device__ __align__(16) unsigned g_xh [NMAX * 64];
__device__ __align__(16) unsigned g_h1h[NMAX * 64];
__device__ __align__(16) unsigned g_h2h[NMAX * 64];
__device__ __align__(16) uint4 g_wfrag[2 * 8192];  // pre-split W fragments
__device__ int g_deg[NMAX];
__device__ int g_start[NMAX];
__device__ int g_cursor[NMAX];
__device__ int g_esrc[EMAX];
__device__ int g_alloc_ctr;

// ---------------------------------------------------------------------------
// fp16 / bf16 helpers
// ---------------------------------------------------------------------------
__device__ __forceinline__ __half2 ash2(unsigned u) {
    return *reinterpret_cast<__half2*>(&u);
}
__device__ __forceinline__ unsigned packh2(float a, float b) {
    __half2 h = __floats2half2_rn(a, b);
    return *reinterpret_cast<unsigned*>(&h);
}
__device__ __forceinline__ float2 unpackh2(unsigned u) {
    return __half22float2(ash2(u));
}

__device__ __forceinline__ unsigned pack_bf16x2(float lo, float hi) {
    unsigned u;
    asm("cvt.rn.bf16x2.f32 %0, %1, %2;" : "=r"(u) : "f"(hi), "f"(lo));
    return u;
}

__device__ __forceinline__ void split2(float x, float y, unsigned& hi, unsigned& lo) {
    hi = pack_bf16x2(x, y);
    float xh = __uint_as_float(hi << 16);
    float yh = __uint_as_float(hi & 0xffff0000u);
    lo = pack_bf16x2(x - xh, y - yh);
}

__device__ __forceinline__ void mma16(float* c, const unsigned* a, unsigned b0, unsigned b1) {
    asm volatile("mma.sync.aligned.m16n8k16.row.col.f32.bf16.bf16.f32 "
        "{%0,%1,%2,%3}, {%4,%5,%6,%7}, {%8,%9}, {%0,%1,%2,%3};"
        : "+f"(c[0]), "+f"(c[1]), "+f"(c[2]), "+f"(c[3])
        : "r"(a[0]), "r"(a[1]), "r"(a[2]), "r"(a[3]), "r"(b0), "r"(b1));
}

// ---------------------------------------------------------------------------
// Convert x (f32) -> fp16
// ---------------------------------------------------------------------------
__global__ void convert_x(const float2* __restrict__ x, unsigned* __restrict__ xh, int n) {
    int i = blockIdx.x * blockDim.x + threadIdx.x;
    if (i < n) {
        float2 v = __ldg(&x[i]);
        xh[i] = packh2(v.x, v.y);
    }
}

// ---------------------------------------------------------------------------
// Prep: split W into bf16 hi/lo fragment order (see layout comment R4).
// ---------------------------------------------------------------------------
__global__ void prep_w(const float* __restrict__ W1l, const float* __restrict__ W1r,
                       const float* __restrict__ Whl, const float* __restrict__ Whr) {
    int idx = blockIdx.x * blockDim.x + threadIdx.x;
    if (idx >= 16384) return;
    int layer = idx >> 13;
    int rem = idx & 8191;
    int S = rem >> 9;
    int T = (rem >> 5) & 15;
    int lane = rem & 31;
    const float* W = (S < 8) ? (layer ? Whl : W1l) : (layer ? Whr : W1r);
    int k0 = (S & 7) * 16;
    int row = T * 8 + (lane >> 2);
    int cc = lane & 3;
    const float* p = W + row * DHH + k0 + 2 * cc;
    unsigned h0, l0, h1, l1;
    split2(__ldg(&p[0]), __ldg(&p[1]), h0, l0);
    split2(__ldg(&p[8]), __ldg(&p[9]), h1, l1);
    g_wfrag[idx] = make_uint4(h0, h1, l0, l1);
}

// ---------------------------------------------------------------------------
// CSR build: histogram -> warp-aggregated range allocation -> fill.
// hist/fill process 4 edges per thread (4 independent atomics in flight).
// ---------------------------------------------------------------------------
__global__ void hist_k(const int* __restrict__ ei, int E, int* __restrict__ deg) {
    int base = (blockIdx.x * blockDim.x + threadIdx.x) * 4;
    if (base == 0) g_alloc_ctr = 0;   // nothing reads it until alloc_k
    if (base + 4 <= E) {
        int4 d4 = *(const int4*)&ei[E + base];
        atomicAdd(&deg[d4.x], 1);
        atomicAdd(&deg[d4.y], 1);
        atomicAdd(&deg[d4.z], 1);
        atomicAdd(&deg[d4.w], 1);
    } else {
        for (int e = base; e < E; e++) atomicAdd(&deg[__ldg(&ei[E + e])], 1);
    }
}

__global__ void alloc_k(const int* __restrict__ deg, int N,
                        int* __restrict__ start, int* __restrict__ cursor) {
    int i = blockIdx.x * blockDim.x + threadIdx.x;
    int lane = threadIdx.x & 31;
    int d = (i < N) ? deg[i] : 0;
    int pref = d;
    #pragma unroll
    for (int off = 1; off < 32; off <<= 1) {
        int v = __shfl_up_sync(0xffffffff, pref, off);
        if (lane >= off) pref += v;
    }
    int total = __shfl_sync(0xffffffff, pref, 31);
    int base = 0;
    if (lane == 31) base = atomicAdd(&g_alloc_ctr, total);
    base = __shfl_sync(0xffffffff, base, 31);
    int mybase = base + pref - d;
    if (i < N) {
        start[i] = mybase;
        cursor[i] = mybase;
    }
}

__global__ void fill_k(const int* __restrict__ ei, int E,
                       int* __restrict__ cursor, int* __restrict__ esrc) {
    int base = (blockIdx.x * blockDim.x + threadIdx.x) * 4;
    if (base + 4 <= E) {
        int4 d4 = *(const int4*)&ei[E + base];
        int4 s4 = *(const int4*)&ei[base];
        int p0 = atomicAdd(&cursor[d4.x], 1);
        int p1 = atomicAdd(&cursor[d4.y], 1);
        int p2 = atomicAdd(&cursor[d4.z], 1);
        int p3 = atomicAdd(&cursor[d4.w], 1);
        esrc[p0] = s4.x;
        esrc[p1] = s4.y;
        esrc[p2] = s4.z;
        esrc[p3] = s4.w;
    } else {
        for (int e = base; e < E; e++) {
            int dst = __ldg(&ei[E + e]);
            int p = atomicAdd(&cursor[dst], 1);
            esrc[p] = __ldg(&ei[e]);
        }
    }
}

// ---------------------------------------------------------------------------
// Gather: one warp per dst node. fp16 feature reads (half the L2 bytes),
// HADD2 partial sums over 4-edge groups, f32 master accumulator, f32 output.
// Lane owns feats [4*lane .. 4*lane+3] = one uint2.
// ---------------------------------------------------------------------------
__global__ void gather_k(const uint2* __restrict__ feath, const int* __restrict__ start,
                         const int* __restrict__ deg, const int* __restrict__ esrc,
                         float4* __restrict__ s, int N) {
    int n = blockIdx.x * 8 + (threadIdx.x >> 5);
    if (n >= N) return;
    int lane = threadIdx.x & 31;
    int beg = __ldg(&start[n]);
    int d = __ldg(&deg[n]);
    int end = beg + d;

    float4 acc = make_float4(0.f, 0.f, 0.f, 0.f);

    int e = beg;
    for (; e + 8 <= end; e += 8) {
        int s0 = __ldg(&esrc[e]),     s1 = __ldg(&esrc[e + 1]);
        int s2 = __ldg(&esrc[e + 2]), s3 = __ldg(&esrc[e + 3]);
        int s4 = __ldg(&esrc[e + 4]), s5 = __ldg(&esrc[e + 5]);
        int s6 = __ldg(&esrc[e + 6]), s7 = __ldg(&esrc[e + 7]);
        uint2 u0 = __ldg(&feath[(long long)s0 * 32 + lane]);
        uint2 u1 = __ldg(&feath[(long long)s1 * 32 + lane]);
        uint2 u2 = __ldg(&feath[(long long)s2 * 32 + lane]);
        uint2 u3 = __ldg(&feath[(long long)s3 * 32 + lane]);
        uint2 u4 = __ldg(&feath[(long long)s4 * 32 + lane]);
        uint2 u5 = __ldg(&feath[(long long)s5 * 32 + lane]);
        uint2 u6 = __ldg(&feath[(long long)s6 * 32 + lane]);
        uint2 u7 = __ldg(&feath[(long long)s7 * 32 + lane]);
        __half2 pa0 = __hadd2(ash2(u0.x), ash2(u1.x));
        __half2 pa1 = __hadd2(ash2(u0.y), ash2(u1.y));
        __half2 qa0 = __hadd2(ash2(u2.x), ash2(u3.x));
        __half2 qa1 = __hadd2(ash2(u2.y), ash2(u3.y));
        pa0 = __hadd2(pa0, qa0); pa1 = __hadd2(pa1, qa1);
        float2 fa0 = __half22float2(pa0), fa1 = __half22float2(pa1);
        acc.x += fa0.x; acc.y += fa0.y; acc.z += fa1.x; acc.w += fa1.y;
        __half2 pb0 = __hadd2(ash2(u4.x), ash2(u5.x));
        __half2 pb1 = __hadd2(ash2(u4.y), ash2(u5.y));
        __half2 qb0 = __hadd2(ash2(u6.x), ash2(u7.x));
        __half2 qb1 = __hadd2(ash2(u6.y), ash2(u7.y));
        pb0 = __hadd2(pb0, qb0); pb1 = __hadd2(pb1, qb1);
        float2 fb0 = __half22float2(pb0), fb1 = __half22float2(pb1);
        acc.x += fb0.x; acc.y += fb0.y; acc.z += fb1.x; acc.w += fb1.y;
    }
    for (; e + 4 <= end; e += 4) {
        int s0 = __ldg(&esrc[e]),     s1 = __ldg(&esrc[e + 1]);
        int s2 = __ldg(&esrc[e + 2]), s3 = __ldg(&esrc[e + 3]);
        uint2 u0 = __ldg(&feath[(long long)s0 * 32 + lane]);
        uint2 u1 = __ldg(&feath[(long long)s1 * 32 + lane]);
        uint2 u2 = __ldg(&feath[(long long)s2 * 32 + lane]);
        uint2 u3 = __ldg(&feath[(long long)s3 * 32 + lane]);
        __half2 p0 = __hadd2(ash2(u0.x), ash2(u1.x));
        __half2 p1 = __hadd2(ash2(u0.y), ash2(u1.y));
        __half2 q0 = __hadd2(ash2(u2.x), ash2(u3.x));
        __half2 q1 = __hadd2(ash2(u2.y), ash2(u3.y));
        p0 = __hadd2(p0, q0); p1 = __hadd2(p1, q1);
        float2 f0 = __half22float2(p0), f1 = __half22float2(p1);
        acc.x += f0.x; acc.y += f0.y; acc.z += f1.x; acc.w += f1.y;
    }
    for (; e < end; e++) {
        int s0 = __ldg(&esrc[e]);
        uint2 u0 = __ldg(&feath[(long long)s0 * 32 + lane]);
        float2 f0 = unpackh2(u0.x), f1 = unpackh2(u0.y);
        acc.x += f0.x; acc.y += f0.y; acc.z += f1.x; acc.w += f1.y;
    }

    float inv = 1.0f / fmaxf((float)d, 1.0f);
    float4 r = make_float4(acc.x * inv, acc.y * inv, acc.z * inv, acc.w * inv);
    s[(long long)n * 32 + lane] = r;
}

// ---------------------------------------------------------------------------
// Fused SAGE layer: C = act([agg | x] . [Wl|Wr]^T + bl), split-bf16 mma.
// Block: 1024 threads / 32 warps. Warp w: rowgroup g = w>>3 (16 rows),
// ntile pair q = w&7 (tiles 2q, 2q+1).
// s input f32, x input fp16-packed; output fp16-packed.
// ---------------------------------------------------------------------------
template <int ACT>
__global__ __launch_bounds__(THREADS_G, 1)
void sage_bf16(const uint2* __restrict__ xh, const float* __restrict__ s,
               const uint4* __restrict__ wfrag, const float* __restrict__ bl,
               unsigned* __restrict__ outh, int N) {
    extern __shared__ char smemraw[];
    uint4*    shW  = (uint4*)smemraw;                       // [KST*NTILES*32] = 8192
    unsigned* shAh = (unsigned*)(smemraw + SMEM_W_BYTES);   // [MT][A_STRIDE]
    unsigned* shAl = shAh + SMEM_A_UINTS;

    int t = threadIdx.x;
    int w = t >> 5, lane = t & 31;
    int r = lane >> 2, c = lane & 3;
    int g = w >> 3;        // row-group 0..3
    int q = w & 7;         // ntile pair 0..7
    int mbase = g * 16;

    // 8192 uint4 entries staged by 1024 threads: 8 iterations.
    #pragma unroll
    for (int i = 0; i < 8; i++)
        shW[t + i * THREADS_G] = __ldg(&wfrag[t + i * THREADS_G]);

    float bias0[2], bias1[2];
    #pragma unroll
    for (int i = 0; i < 2; i++) {
        int colg = (q * 2 + i) * 8 + 2 * c;
        bias0[i] = __ldg(&bl[colg]);
        bias1[i] = __ldg(&bl[colg + 1]);
    }

    int mtiles = (N + MT - 1) / MT;
    for (int tile = blockIdx.x; tile < mtiles; tile += gridDim.x) {
        __syncthreads();
        int n0 = tile * MT;

        #pragma unroll
        for (int i = 0; i < 4; i++) {
            int flat = t + i * THREADS_G;
            int row = flat >> 6;
            int c4 = flat & 63;
            int node = n0 + row;
            float4 v = make_float4(0.f, 0.f, 0.f, 0.f);
            if (node < N) {
                if (c4 < 32) {
                    v = __ldg((const float4*)s + (long long)node * 32 + c4);
                } else {
                    uint2 u = __ldg(&xh[(long long)node * 32 + (c4 - 32)]);
                    float2 a = unpackh2(u.x), b = unpackh2(u.y);
                    v = make_float4(a.x, a.y, b.x, b.y);
                }
            }
            unsigned h01, l01, h23, l23;
            split2(v.x, v.y, h01, l01);
            split2(v.z, v.w, h23, l23);
            int base = row * A_STRIDE + c4 * 2;
            *(uint2*)&shAh[base] = make_uint2(h01, h23);
            *(uint2*)&shAl[base] = make_uint2(l01, l23);
        }
        __syncthreads();

        float acc[2][4];
        #pragma unroll
        for (int T = 0; T < 2; T++)
            acc[T][0] = acc[T][1] = acc[T][2] = acc[T][3] = 0.f;

        #pragma unroll 4
        for (int S = 0; S < KST; S++) {
            int ra = (mbase + r) * A_STRIDE + S * 8 + c;
            int rb = (mbase + r + 8) * A_STRIDE + S * 8 + c;
            unsigned ah[4], al[4];
            ah[0] = shAh[ra]; ah[1] = shAh[rb]; ah[2] = shAh[ra + 4]; ah[3] = shAh[rb + 4];
            al[0] = shAl[ra]; al[1] = shAl[rb]; al[2] = shAl[ra + 4]; al[3] = shAl[rb + 4];
            #pragma unroll
            for (int T = 0; T < 2; T++) {
                uint4 b = shW[(S * NTILES + q * 2 + T) * 32 + lane];
                mma16(acc[T], al, b.x, b.y);   // al*bh
                mma16(acc[T], ah, b.z, b.w);   // ah*bl
                mma16(acc[T], ah, b.x, b.y);   // ah*bh
            }
        }

        #pragma unroll
        for (int T = 0; T < 2; T++) {
            int colg = (q * 2 + T) * 8 + 2 * c;
            float v0 = acc[T][0] + bias0[T], v1 = acc[T][1] + bias1[T];
            float v2 = acc[T][2] + bias0[T], v3 = acc[T][3] + bias1[T];
            if (ACT == 0) {
                v0 = fmaxf(v0, 0.f); v1 = fmaxf(v1, 0.f);
                v2 = fmaxf(v2, 0.f); v3 = fmaxf(v3, 0.f);
            } else {
                v0 = (v0 > 0.f) ? v0 : expm1f(v0);
                v1 = (v1 > 0.f) ? v1 : expm1f(v1);
                v2 = (v2 > 0.f) ? v2 : expm1f(v2);
                v3 = (v3 > 0.f) ? v3 : expm1f(v3);
            }
            int node0 = n0 + mbase + r;
            int cw = colg >> 1;                 // uint word index within row
            if (node0 < N)
                outh[(long long)node0 * 64 + cw] = packh2(v0, v1);
            if (node0 + 8 < N)
                outh[(long long)(node0 + 8) * 64 + cw] = packh2(v2, v3);
        }
    }
}

// ---------------------------------------------------------------------------
// Output layer (DOUT=8) + log_softmax. One warp per node.
// Lane owns feats [4*lane..4*lane+3]; weights via vector LDG.128 (coalesced).
// ---------------------------------------------------------------------------
__global__ void sage_out_k(const uint2* __restrict__ xh, const float4* __restrict__ s,
                           const float* __restrict__ Wl, const float* __restrict__ bl,
                           const float* __restrict__ Wr,
                           float* __restrict__ out, int N) {
    long long tid = (long long)blockIdx.x * blockDim.x + threadIdx.x;
    int n = (int)(tid >> 5);
    if (n >= N) return;
    int lane = (int)(tid & 31);

    float4 sv = __ldg(&s[(long long)n * 32 + lane]);
    uint2 xu = __ldg(&xh[(long long)n * 32 + lane]);
    float2 x01 = unpackh2(xu.x), x23 = unpackh2(xu.y);

    float acc[8];
    #pragma unroll
    for (int j = 0; j < 8; j++) {
        float4 wl = __ldg((const float4*)(Wl + j * DHH) + lane);
        float4 wr = __ldg((const float4*)(Wr + j * DHH) + lane);
        acc[j] = sv.x * wl.x + sv.y * wl.y + sv.z * wl.z + sv.w * wl.w
               + x01.x * wr.x + x01.y * wr.y + x23.x * wr.z + x23.y * wr.w;
    }

    #pragma unroll
    for (int j = 0; j < 8; j++) {
        #pragma unroll
        for (int off = 16; off > 0; off >>= 1)
            acc[j] += __shfl_xor_sync(0xffffffff, acc[j], off);
    }

    if (lane == 0) {
        float h[8];
        float m = -1e30f;
        #pragma unroll
        for (int j = 0; j < 8; j++) {
            h[j] = acc[j] + bl[j];
            m = fmaxf(m, h[j]);
        }
        float sum = 0.0f;
        #pragma unroll
        for (int j = 0; j < 8; j++) sum += expf(h[j] - m);
        float lse = logf(sum) + m;
        #pragma unroll
        for (int j = 0; j < 8; j++) out[(long long)n * 8 + j] = h[j] - lse;
    }
}

// ---------------------------------------------------------------------------
extern "C" void kernel_launch(void* const* d_in, const int* in_sizes, int n_in,
                              void* d_out, int out_size) {
    const float* x   = (const float*)d_in[0];
    const int*   ei  = (const int*)d_in[1];
    // d_in[2] = edge_attr, unused
    const float* W1l = (const float*)d_in[3];
    const float* b1l = (const float*)d_in[4];
    const float* W1r = (const float*)d_in[5];
    const float* Whl = (const float*)d_in[6];
    const float* bhl = (const float*)d_in[7];
    const float* Whr = (const float*)d_in[8];
    const float* W2l = (const float*)d_in[9];
    const float* b2l = (const float*)d_in[10];
    const float* W2r = (const float*)d_in[11];
    float* out = (float*)d_out;

    int N = in_sizes[0] / DHH;
    int E = in_sizes[1] / 2;

    float4* s;
    unsigned *xh, *h1h, *h2h;
    uint4* wfrag;
    int *deg, *start, *cursor, *esrc;
    cudaGetSymbolAddress((void**)&s, g_s);
    cudaGetSymbolAddress((void**)&xh, g_xh);
    cudaGetSymbolAddress((void**)&h1h, g_h1h);
    cudaGetSymbolAddress((void**)&h2h, g_h2h);
    cudaGetSymbolAddress((void**)&wfrag, g_wfrag);
    cudaGetSymbolAddress((void**)&deg, g_deg);
    cudaGetSymbolAddress((void**)&start, g_start);
    cudaGetSymbolAddress((void**)&cursor, g_cursor);
    cudaGetSymbolAddress((void**)&esrc, g_esrc);

    cudaFuncSetAttribute(sage_bf16<0>, cudaFuncAttributeMaxDynamicSharedMemorySize,
                         SMEM_TOTAL_BYTES);
    cudaFuncSetAttribute(sage_bf16<1>, cudaFuncAttributeMaxDynamicSharedMemorySize,
                         SMEM_TOTAL_BYTES);

    int e4grid = (E / 4 + 255) / 256 + 1;
    int ngrid = (N + 255) / 256;
    int cgrid = (N * 64 + 255) / 256;
    int ggrid = 148;
    int agrid = (N + 7) / 8;
    int ogrid = (int)(((long long)N * 32 + 255) / 256);

    // CSR build + fp16 conversion of x
    cudaMemsetAsync(deg, 0, (size_t)N * sizeof(int), 0);
    convert_x<<<cgrid, 256>>>((const float2*)x, xh, N * 64);
    hist_k<<<e4grid, 256>>>(ei, E, deg);
    alloc_k<<<ngrid, 256>>>(deg, N, start, cursor);
    fill_k<<<e4grid, 256>>>(ei, E, cursor, esrc);

    // Layer 1 (prep_w needs to finish only before sage_bf16<0>)
    gather_k<<<agrid, 256>>>((const uint2*)xh, start, deg, esrc, s, N);
    prep_w<<<64, 256>>>(W1l, W1r, Whl, Whr);
    sage_bf16<0><<<ggrid, THREADS_G, SMEM_TOTAL_BYTES>>>((const uint2*)xh, (const float*)s,
                                                         wfrag, b1l, h1h, N);

    // Layer 2
    gather_k<<<agrid, 256>>>((const uint2*)h1h, start, deg, esrc, s, N);
    sage_bf16<1><<<ggrid, THREADS_G, SMEM_TOTAL_BYTES>>>((const uint2*)h1h, (const float*)s,
                                                         wfrag + 8192, bhl, h2h, N);

    // Layer 3
    gather_k<<<agrid, 256>>>((const uint2*)h2h, start, deg, esrc, s, N);
    sage_out_k<<<ogrid, 256>>>((const uint2*)h2h, s, W2l, b2l, W2r, out, N);
}